// round 14
// baseline (speedup 1.0000x reference)
#include <cuda_runtime.h>

#define BB   4
#define NN   2048
#define DIN  128
#define DOUT 128      // H*HD
#define HH   4
#define HD   32
#define NWRD (NN/32)  // 64 words per adjT row

#define NSPLIT 8
#define JCHUNK (NN/NSPLIT)   // 256 j per warp
#define TJS    16            // j tile per warp per stage (double-buffered)
#define NSTAGE (JCHUNK/TJS)  // 16 stages

#define LOG2E 1.4426950408889634f

// ---------------- scratch (static device globals; no allocation) -------------
__device__ float    g_h [BB*NN*DOUT];   // 4 MB   h = x @ W^T
__device__ float    g_ei[BB*NN*HH];     // 128 KB (pre-scaled by log2e)
__device__ float    g_ej[BB*NN*HH];     // 128 KB (pre-scaled by log2e)
__device__ unsigned g_adjT[NN*NWRD];    // 512 KB, bit l of word [j][iw] = adj[iw*32+l][j]

// ---------------- kernel 1: h = x @ W^T + fused ei/ej ------------------------
// 32-row tiles, 128 threads -> 256 blocks (was 128) for latency hiding.
__global__ void __launch_bounds__(128) gemm_h_kernel(const float* __restrict__ x,
                                                     const float* __restrict__ W,
                                                     const float* __restrict__ a) {
    __shared__ __align__(16) float x_s[32][36];
    __shared__ __align__(16) float w_s[32][132];

    const int tid = threadIdx.x;
    const int cg  = tid & 31;       // cols cg*4 .. cg*4+3
    const int rg  = tid >> 5;       // rows rg*8 .. rg*8+7 (4 warps)
    const int row0 = blockIdx.x * 32;

    float acc[8][4];
    #pragma unroll
    for (int r = 0; r < 8; ++r)
        #pragma unroll
        for (int c = 0; c < 4; ++c) acc[r][c] = 0.f;

    for (int k0 = 0; k0 < DIN; k0 += 32) {
        // stage x tile (32 rows x 32 k) = 256 float4, 128 threads -> 2 iters
        #pragma unroll
        for (int it = 0; it < 2; ++it) {
            int f = tid + it * 128;
            int r = f >> 3, q = f & 7;
            float4 v = *(const float4*)(x + (size_t)(row0 + r) * DIN + k0 + q * 4);
            *(float4*)&x_s[r][q * 4] = v;
        }
        // stage W tile transposed: thread c loads W[c][k0..k0+31]
        {
            const float* wp = W + (size_t)tid * DIN + k0;
            #pragma unroll
            for (int kk = 0; kk < 32; kk += 4) {
                float4 v = *(const float4*)(wp + kk);
                w_s[kk + 0][tid] = v.x;
                w_s[kk + 1][tid] = v.y;
                w_s[kk + 2][tid] = v.z;
                w_s[kk + 3][tid] = v.w;
            }
        }
        __syncthreads();
        #pragma unroll
        for (int k = 0; k < 32; ++k) {
            float4 wv = *(const float4*)&w_s[k][cg * 4];
            #pragma unroll
            for (int r = 0; r < 8; ++r) {
                float xv = x_s[rg * 8 + r][k];
                acc[r][0] += xv * wv.x;
                acc[r][1] += xv * wv.y;
                acc[r][2] += xv * wv.z;
                acc[r][3] += xv * wv.w;
            }
        }
        __syncthreads();
    }

    // store h
    #pragma unroll
    for (int r = 0; r < 8; ++r) {
        float4 v = make_float4(acc[r][0], acc[r][1], acc[r][2], acc[r][3]);
        *(float4*)(g_h + (size_t)(row0 + rg * 8 + r) * DOUT + cg * 4) = v;
    }

    // fused ei/ej: head = cg>>3, cols (cg&7)*4..+3, reduce over 8-lane groups
    const int head = cg >> 3;
    const int c0   = (cg & 7) * 4;
    float a1v[4], a2v[4];
    #pragma unroll
    for (int k = 0; k < 4; ++k) {
        a1v[k] = a[head * 2 * HD + c0 + k];
        a2v[k] = a[head * 2 * HD + HD + c0 + k];
    }
    #pragma unroll
    for (int r = 0; r < 8; ++r) {
        float p1 = acc[r][0] * a1v[0] + acc[r][1] * a1v[1]
                 + acc[r][2] * a1v[2] + acc[r][3] * a1v[3];
        float p2 = acc[r][0] * a2v[0] + acc[r][1] * a2v[1]
                 + acc[r][2] * a2v[2] + acc[r][3] * a2v[3];
        p1 += __shfl_down_sync(0xffffffffu, p1, 4, 8);
        p1 += __shfl_down_sync(0xffffffffu, p1, 2, 8);
        p1 += __shfl_down_sync(0xffffffffu, p1, 1, 8);
        p2 += __shfl_down_sync(0xffffffffu, p2, 4, 8);
        p2 += __shfl_down_sync(0xffffffffu, p2, 2, 8);
        p2 += __shfl_down_sync(0xffffffffu, p2, 1, 8);
        if ((cg & 7) == 0) {
            int bn = row0 + rg * 8 + r;
            g_ei[bn * HH + head] = p1 * LOG2E;
            g_ej[bn * HH + head] = p2 * LOG2E;
        }
    }
}

// ---------------- kernel 2: pack adj transposed into bitmask -----------------
__global__ void adjt_kernel(const int* __restrict__ adj) {
    __shared__ int s[32][33];
    const int tx = threadIdx.x, ty = threadIdx.y;
    const int j0 = blockIdx.x * 32, i0 = blockIdx.y * 32;
    s[ty][tx] = adj[(size_t)(i0 + ty) * NN + j0 + tx];
    __syncthreads();
    int val = s[tx][ty];
    unsigned m = __ballot_sync(0xffffffffu, val != 0);
    if (tx == 0) g_adjT[(size_t)(j0 + ty) * NWRD + (i0 >> 5)] = m;
}

// ---------------- kernel 3: fused masked-softmax attention -------------------
// block = 256 thr = 8 warps. Warp w owns j-split [w*256,(w+1)*256), covers all
// 64 i (2 i-groups per lane). Warp-private DOUBLE-BUFFERED cp.async tiles —
// prefetch of tile s+1 overlaps consumption of tile s. No in-loop barriers.
__global__ void __launch_bounds__(256, 2) gat_main_kernel(float* __restrict__ out) {
    __shared__ __align__(16) union {
        struct {
            float    h  [NSPLIT][2][TJS][HD];   // 32 KB
            float    ej [NSPLIT][2][TJS];       // 1 KB
            unsigned adj[NSPLIT][2][TJS][2];    // 2 KB
        } st;
        unsigned long long red[4][64][17];      // 34 KB (aliased, post-loop)
    } sm;

    const int b   = blockIdx.z;
    const int hh  = blockIdx.y;
    const int i0  = blockIdx.x * 64;
    const int w   = threadIdx.x >> 5;
    const int l   = threadIdx.x & 31;
    const int iw0 = i0 >> 5;
    const unsigned lanebit = 1u << l;

    const float ei0 = g_ei[((size_t)b * NN + i0 + l)      * HH + hh];
    const float ei1 = g_ei[((size_t)b * NN + i0 + 32 + l) * HH + hh];

    unsigned long long acc0[16], acc1[16];
    #pragma unroll
    for (int p = 0; p < 16; ++p) { acc0[p] = 0ull; acc1[p] = 0ull; }
    float denom0 = 0.f, denom1 = 0.f;

    const int jbase = w * JCHUNK;
    const unsigned hb[2]  = {
        (unsigned)__cvta_generic_to_shared(&sm.st.h[w][0][0][0]),
        (unsigned)__cvta_generic_to_shared(&sm.st.h[w][1][0][0]) };
    const unsigned ejb[2] = {
        (unsigned)__cvta_generic_to_shared(&sm.st.ej[w][0][0]),
        (unsigned)__cvta_generic_to_shared(&sm.st.ej[w][1][0]) };
    const unsigned adb[2] = {
        (unsigned)__cvta_generic_to_shared(&sm.st.adj[w][0][0][0]),
        (unsigned)__cvta_generic_to_shared(&sm.st.adj[w][1][0][0]) };

    // prefetch helper (macro to keep everything in registers)
    #define PREFETCH(BUF, JG)                                                     \
        do {                                                                      \
            const char* gsrc = (const char*)(g_h + ((size_t)b * NN + (JG)) * DOUT \
                                             + hh * HD);                          \
            _Pragma("unroll")                                                     \
            for (int it = 0; it < 4; ++it) {                                      \
                int t = l + it * 32;                                              \
                int row = t >> 3, q = t & 7;                                      \
                const char* gp = gsrc + (size_t)row * (DOUT * 4) + q * 16;        \
                unsigned sp = hb[BUF] + (unsigned)(row * (HD * 4) + q * 16);      \
                asm volatile("cp.async.ca.shared.global [%0], [%1], 16;"          \
                             :: "r"(sp), "l"(gp));                                \
            }                                                                     \
            if (l < TJS) {                                                        \
                const char* ep = (const char*)(g_ej                               \
                    + ((size_t)b * NN + (JG) + l) * HH + hh);                     \
                asm volatile("cp.async.ca.shared.global [%0], [%1], 4;"           \
                             :: "r"(ejb[BUF] + l * 4u), "l"(ep));                 \
                const char* ap = (const char*)(g_adjT                             \
                    + (size_t)((JG) + l) * NWRD + iw0);                           \
                asm volatile("cp.async.ca.shared.global [%0], [%1], 8;"           \
                             :: "r"(adb[BUF] + l * 8u), "l"(ap));                 \
            }                                                                     \
            asm volatile("cp.async.commit_group;");                               \
        } while (0)

    PREFETCH(0, jbase);

    for (int st = 0; st < NSTAGE; ++st) {
        const int buf = st & 1;
        if (st + 1 < NSTAGE) {
            PREFETCH(1 - buf, jbase + (st + 1) * TJS);
            asm volatile("cp.async.wait_group 1;" ::: "memory");
        } else {
            asm volatile("cp.async.wait_group 0;" ::: "memory");
        }
        __syncwarp();

        const float*    ejp  = &sm.st.ej[w][buf][0];
        const unsigned* adjp = &sm.st.adj[w][buf][0][0];
        const unsigned  hbase = hb[buf];

        #pragma unroll 4
        for (int jj = 0; jj < TJS; ++jj) {
            float ejv = ejp[jj];                            // broadcast LDS
            unsigned m0 = adjp[jj * 2];                     // broadcast LDS.64
            unsigned m1 = adjp[jj * 2 + 1];
            float t0 = ei0 + ejv;
            float t1 = ei1 + ejv;
            float lk0 = fmaxf(t0, 0.2f * t0);
            float lk1 = fmaxf(t1, 0.2f * t1);
            float e0, e1;
            asm("ex2.approx.f32 %0, %1;" : "=f"(e0) : "f"(lk0));
            asm("ex2.approx.f32 %0, %1;" : "=f"(e1) : "f"(lk1));
            float w0 = (m0 & lanebit) ? e0 : 0.f;
            float w1 = (m1 & lanebit) ? e1 : 0.f;
            denom0 += w0;
            denom1 += w1;
            unsigned long long w20, w21;
            asm("mov.b64 %0, {%1, %1};" : "=l"(w20) : "f"(w0));
            asm("mov.b64 %0, {%1, %1};" : "=l"(w21) : "f"(w1));
            unsigned addr = hbase + (unsigned)(jj * (HD * 4));
            #pragma unroll
            for (int p = 0; p < 8; ++p) {
                unsigned long long a0, a1;
                asm volatile("ld.shared.v2.b64 {%0, %1}, [%2];"
                             : "=l"(a0), "=l"(a1) : "r"(addr + p * 16));
                asm("fma.rn.f32x2 %0, %1, %2, %0;" : "+l"(acc0[2*p])   : "l"(w20), "l"(a0));
                asm("fma.rn.f32x2 %0, %1, %2, %0;" : "+l"(acc0[2*p+1]) : "l"(w20), "l"(a1));
                asm("fma.rn.f32x2 %0, %1, %2, %0;" : "+l"(acc1[2*p])   : "l"(w21), "l"(a0));
                asm("fma.rn.f32x2 %0, %1, %2, %0;" : "+l"(acc1[2*p+1]) : "l"(w21), "l"(a1));
            }
        }
        __syncwarp();   // all lanes done with buf before it is refilled
    }
    #undef PREFETCH

    // ---------------- cross-warp tree reduction (3 rounds) -------------------
    #define WRITE_P(BUFI)                                                        \
        do {                                                                     \
            unsigned long long* d0 = &sm.red[BUFI][l][0];                        \
            unsigned long long* d1 = &sm.red[BUFI][32 + l][0];                   \
            _Pragma("unroll")                                                    \
            for (int p = 0; p < 16; ++p) { d0[p] = acc0[p]; d1[p] = acc1[p]; }   \
            ((float*)&d0[16])[0] = denom0;                                       \
            ((float*)&d1[16])[0] = denom1;                                       \
        } while (0)
    #define ADD_P(BUFI)                                                         \
        do {                                                                    \
            const unsigned long long* s0 = &sm.red[BUFI][l][0];                 \
            const unsigned long long* s1 = &sm.red[BUFI][32 + l][0];            \
            _Pragma("unroll")                                                   \
            for (int p = 0; p < 16; ++p) {                                      \
                asm("add.rn.f32x2 %0, %0, %1;" : "+l"(acc0[p]) : "l"(s0[p]));   \
                asm("add.rn.f32x2 %0, %0, %1;" : "+l"(acc1[p]) : "l"(s1[p]));   \
            }                                                                   \
            denom0 += ((const float*)&s0[16])[0];                               \
            denom1 += ((const float*)&s1[16])[0];                               \
        } while (0)

    __syncthreads();
    if (w & 1) WRITE_P(w >> 1);
    __syncthreads();
    if (!(w & 1)) ADD_P(w >> 1);
    __syncthreads();
    if (w == 2) WRITE_P(0);
    if (w == 6) WRITE_P(1);
    __syncthreads();
    if (w == 0) ADD_P(0);
    if (w == 4) ADD_P(1);
    __syncthreads();
    if (w == 4) WRITE_P(0);
    __syncthreads();

    if (w == 0) {
        ADD_P(0);
        const float inv0 = 1.0f / denom0;
        const float inv1 = 1.0f / denom1;
        float* dst0 = out + ((size_t)b * NN + i0 + l)      * DOUT + hh * HD;
        float* dst1 = out + ((size_t)b * NN + i0 + 32 + l) * DOUT + hh * HD;
        #pragma unroll
        for (int p = 0; p < 8; ++p) {
            float x0, y0, x1, y1;
            asm("mov.b64 {%0, %1}, %2;" : "=f"(x0), "=f"(y0) : "l"(acc0[2*p]));
            asm("mov.b64 {%0, %1}, %2;" : "=f"(x1), "=f"(y1) : "l"(acc0[2*p+1]));
            *(float4*)(dst0 + p * 4) = make_float4(x0*inv0, y0*inv0, x1*inv0, y1*inv0);
            asm("mov.b64 {%0, %1}, %2;" : "=f"(x0), "=f"(y0) : "l"(acc1[2*p]));
            asm("mov.b64 {%0, %1}, %2;" : "=f"(x1), "=f"(y1) : "l"(acc1[2*p+1]));
            *(float4*)(dst1 + p * 4) = make_float4(x0*inv1, y0*inv1, x1*inv1, y1*inv1);
        }
    }
    #undef WRITE_P
    #undef ADD_P
}

// ---------------- launch ------------------------------------------------------
extern "C" void kernel_launch(void* const* d_in, const int* in_sizes, int n_in,
                              void* d_out, int out_size) {
    const float* x   = (const float*)d_in[0];   // (B,N,DIN) f32
    const int*   adj = (const int*)  d_in[1];   // (N,N) i32
    const float* W   = (const float*)d_in[2];   // (H*HD, DIN) f32
    const float* a   = (const float*)d_in[3];   // (H, 2*HD, 1) f32
    float* out = (float*)d_out;                 // (B,N,H*HD) f32

    gemm_h_kernel<<<(BB * NN) / 32, 128>>>(x, W, a);
    adjt_kernel<<<dim3(NN / 32, NN / 32), dim3(32, 32)>>>(adj);
    gat_main_kernel<<<dim3(NN / 64, HH, BB), 256>>>(out);
}

// round 15
// speedup vs baseline: 1.0439x; 1.0439x over previous
#include <cuda_runtime.h>

#define BB   4
#define NN   2048
#define DIN  128
#define DOUT 128      // H*HD
#define HH   4
#define HD   32
#define NWRD (NN/32)  // 64 words per adjT row

#define NSPLIT 8
#define JCHUNK (NN/NSPLIT)   // 256 j per warp
#define TJS    16            // j tile per warp per stage (double-buffered)
#define NSTAGE (JCHUNK/TJS)  // 16 stages

#define LOG2E 1.4426950408889634f

// ---------------- scratch (static device globals; no allocation) -------------
__device__ float    g_h [BB*NN*DOUT];   // 4 MB   h = x @ W^T
__device__ float    g_ei[BB*NN*HH];     // 128 KB (pre-scaled by log2e)
__device__ float    g_ej[BB*NN*HH];     // 128 KB (pre-scaled by log2e)
__device__ unsigned g_adjT[NN*NWRD];    // 512 KB, bit l of word [j][iw] = adj[iw*32+l][j]

// ---------------- kernel 1: h = x @ W^T + fused ei/ej ------------------------
// 32-row tiles, 128 threads -> 256 blocks (was 128) for latency hiding.
__global__ void __launch_bounds__(128) gemm_h_kernel(const float* __restrict__ x,
                                                     const float* __restrict__ W,
                                                     const float* __restrict__ a) {
    __shared__ __align__(16) float x_s[32][36];
    __shared__ __align__(16) float w_s[32][132];

    const int tid = threadIdx.x;
    const int cg  = tid & 31;       // cols cg*4 .. cg*4+3
    const int rg  = tid >> 5;       // rows rg*8 .. rg*8+7 (4 warps)
    const int row0 = blockIdx.x * 32;

    float acc[8][4];
    #pragma unroll
    for (int r = 0; r < 8; ++r)
        #pragma unroll
        for (int c = 0; c < 4; ++c) acc[r][c] = 0.f;

    for (int k0 = 0; k0 < DIN; k0 += 32) {
        // stage x tile (32 rows x 32 k) = 256 float4, 128 threads -> 2 iters
        #pragma unroll
        for (int it = 0; it < 2; ++it) {
            int f = tid + it * 128;
            int r = f >> 3, q = f & 7;
            float4 v = *(const float4*)(x + (size_t)(row0 + r) * DIN + k0 + q * 4);
            *(float4*)&x_s[r][q * 4] = v;
        }
        // stage W tile transposed: thread c loads W[c][k0..k0+31]
        {
            const float* wp = W + (size_t)tid * DIN + k0;
            #pragma unroll
            for (int kk = 0; kk < 32; kk += 4) {
                float4 v = *(const float4*)(wp + kk);
                w_s[kk + 0][tid] = v.x;
                w_s[kk + 1][tid] = v.y;
                w_s[kk + 2][tid] = v.z;
                w_s[kk + 3][tid] = v.w;
            }
        }
        __syncthreads();
        #pragma unroll
        for (int k = 0; k < 32; ++k) {
            float4 wv = *(const float4*)&w_s[k][cg * 4];
            #pragma unroll
            for (int r = 0; r < 8; ++r) {
                float xv = x_s[rg * 8 + r][k];
                acc[r][0] += xv * wv.x;
                acc[r][1] += xv * wv.y;
                acc[r][2] += xv * wv.z;
                acc[r][3] += xv * wv.w;
            }
        }
        __syncthreads();
    }

    // store h
    #pragma unroll
    for (int r = 0; r < 8; ++r) {
        float4 v = make_float4(acc[r][0], acc[r][1], acc[r][2], acc[r][3]);
        *(float4*)(g_h + (size_t)(row0 + rg * 8 + r) * DOUT + cg * 4) = v;
    }

    // fused ei/ej: head = cg>>3, cols (cg&7)*4..+3, reduce over 8-lane groups
    const int head = cg >> 3;
    const int c0   = (cg & 7) * 4;
    float a1v[4], a2v[4];
    #pragma unroll
    for (int k = 0; k < 4; ++k) {
        a1v[k] = a[head * 2 * HD + c0 + k];
        a2v[k] = a[head * 2 * HD + HD + c0 + k];
    }
    #pragma unroll
    for (int r = 0; r < 8; ++r) {
        float p1 = acc[r][0] * a1v[0] + acc[r][1] * a1v[1]
                 + acc[r][2] * a1v[2] + acc[r][3] * a1v[3];
        float p2 = acc[r][0] * a2v[0] + acc[r][1] * a2v[1]
                 + acc[r][2] * a2v[2] + acc[r][3] * a2v[3];
        p1 += __shfl_down_sync(0xffffffffu, p1, 4, 8);
        p1 += __shfl_down_sync(0xffffffffu, p1, 2, 8);
        p1 += __shfl_down_sync(0xffffffffu, p1, 1, 8);
        p2 += __shfl_down_sync(0xffffffffu, p2, 4, 8);
        p2 += __shfl_down_sync(0xffffffffu, p2, 2, 8);
        p2 += __shfl_down_sync(0xffffffffu, p2, 1, 8);
        if ((cg & 7) == 0) {
            int bn = row0 + rg * 8 + r;
            g_ei[bn * HH + head] = p1 * LOG2E;
            g_ej[bn * HH + head] = p2 * LOG2E;
        }
    }
}

// ---------------- kernel 2: pack adj transposed into bitmask -----------------
__global__ void adjt_kernel(const int* __restrict__ adj) {
    __shared__ int s[32][33];
    const int tx = threadIdx.x, ty = threadIdx.y;
    const int j0 = blockIdx.x * 32, i0 = blockIdx.y * 32;
    s[ty][tx] = adj[(size_t)(i0 + ty) * NN + j0 + tx];
    __syncthreads();
    int val = s[tx][ty];
    unsigned m = __ballot_sync(0xffffffffu, val != 0);
    if (tx == 0) g_adjT[(size_t)(j0 + ty) * NWRD + (i0 >> 5)] = m;
}

// ---------------- kernel 3: fused masked-softmax attention -------------------
// block = 256 thr = 8 warps. Warp w owns j-split [w*256,(w+1)*256), covers all
// 64 i (2 i-groups per lane). Warp-private DOUBLE-BUFFERED cp.async tiles —
// prefetch of tile s+1 overlaps consumption of tile s. No in-loop barriers.
__global__ void __launch_bounds__(256, 2) gat_main_kernel(float* __restrict__ out) {
    __shared__ __align__(16) union {
        struct {
            float    h  [NSPLIT][2][TJS][HD];   // 32 KB
            float    ej [NSPLIT][2][TJS];       // 1 KB
            unsigned adj[NSPLIT][2][TJS][2];    // 2 KB
        } st;
        unsigned long long red[4][64][17];      // 34 KB (aliased, post-loop)
    } sm;

    const int b   = blockIdx.z;
    const int hh  = blockIdx.y;
    const int i0  = blockIdx.x * 64;
    const int w   = threadIdx.x >> 5;
    const int l   = threadIdx.x & 31;
    const int iw0 = i0 >> 5;
    const unsigned lanebit = 1u << l;

    const float ei0 = g_ei[((size_t)b * NN + i0 + l)      * HH + hh];
    const float ei1 = g_ei[((size_t)b * NN + i0 + 32 + l) * HH + hh];

    unsigned long long acc0[16], acc1[16];
    #pragma unroll
    for (int p = 0; p < 16; ++p) { acc0[p] = 0ull; acc1[p] = 0ull; }
    float denom0 = 0.f, denom1 = 0.f;

    const int jbase = w * JCHUNK;
    const unsigned hb[2]  = {
        (unsigned)__cvta_generic_to_shared(&sm.st.h[w][0][0][0]),
        (unsigned)__cvta_generic_to_shared(&sm.st.h[w][1][0][0]) };
    const unsigned ejb[2] = {
        (unsigned)__cvta_generic_to_shared(&sm.st.ej[w][0][0]),
        (unsigned)__cvta_generic_to_shared(&sm.st.ej[w][1][0]) };
    const unsigned adb[2] = {
        (unsigned)__cvta_generic_to_shared(&sm.st.adj[w][0][0][0]),
        (unsigned)__cvta_generic_to_shared(&sm.st.adj[w][1][0][0]) };

    // prefetch helper (macro to keep everything in registers)
    #define PREFETCH(BUF, JG)                                                     \
        do {                                                                      \
            const char* gsrc = (const char*)(g_h + ((size_t)b * NN + (JG)) * DOUT \
                                             + hh * HD);                          \
            _Pragma("unroll")                                                     \
            for (int it = 0; it < 4; ++it) {                                      \
                int t = l + it * 32;                                              \
                int row = t >> 3, q = t & 7;                                      \
                const char* gp = gsrc + (size_t)row * (DOUT * 4) + q * 16;        \
                unsigned sp = hb[BUF] + (unsigned)(row * (HD * 4) + q * 16);      \
                asm volatile("cp.async.ca.shared.global [%0], [%1], 16;"          \
                             :: "r"(sp), "l"(gp));                                \
            }                                                                     \
            if (l < TJS) {                                                        \
                const char* ep = (const char*)(g_ej                               \
                    + ((size_t)b * NN + (JG) + l) * HH + hh);                     \
                asm volatile("cp.async.ca.shared.global [%0], [%1], 4;"           \
                             :: "r"(ejb[BUF] + l * 4u), "l"(ep));                 \
                const char* ap = (const char*)(g_adjT                             \
                    + (size_t)((JG) + l) * NWRD + iw0);                           \
                asm volatile("cp.async.ca.shared.global [%0], [%1], 8;"           \
                             :: "r"(adb[BUF] + l * 8u), "l"(ap));                 \
            }                                                                     \
            asm volatile("cp.async.commit_group;");                               \
        } while (0)

    PREFETCH(0, jbase);

    for (int st = 0; st < NSTAGE; ++st) {
        const int buf = st & 1;
        if (st + 1 < NSTAGE) {
            PREFETCH(1 - buf, jbase + (st + 1) * TJS);
            asm volatile("cp.async.wait_group 1;" ::: "memory");
        } else {
            asm volatile("cp.async.wait_group 0;" ::: "memory");
        }
        __syncwarp();

        const float*    ejp  = &sm.st.ej[w][buf][0];
        const unsigned* adjp = &sm.st.adj[w][buf][0][0];
        const unsigned  hbase = hb[buf];

        #pragma unroll 4
        for (int jj = 0; jj < TJS; ++jj) {
            float ejv = ejp[jj];                            // broadcast LDS
            unsigned m0 = adjp[jj * 2];                     // broadcast LDS.64
            unsigned m1 = adjp[jj * 2 + 1];
            float t0 = ei0 + ejv;
            float t1 = ei1 + ejv;
            float lk0 = fmaxf(t0, 0.2f * t0);
            float lk1 = fmaxf(t1, 0.2f * t1);
            float e0, e1;
            asm("ex2.approx.f32 %0, %1;" : "=f"(e0) : "f"(lk0));
            asm("ex2.approx.f32 %0, %1;" : "=f"(e1) : "f"(lk1));
            float w0 = (m0 & lanebit) ? e0 : 0.f;
            float w1 = (m1 & lanebit) ? e1 : 0.f;
            denom0 += w0;
            denom1 += w1;
            unsigned long long w20, w21;
            asm("mov.b64 %0, {%1, %1};" : "=l"(w20) : "f"(w0));
            asm("mov.b64 %0, {%1, %1};" : "=l"(w21) : "f"(w1));
            unsigned addr = hbase + (unsigned)(jj * (HD * 4));
            #pragma unroll
            for (int p = 0; p < 8; ++p) {
                unsigned long long a0, a1;
                asm volatile("ld.shared.v2.b64 {%0, %1}, [%2];"
                             : "=l"(a0), "=l"(a1) : "r"(addr + p * 16));
                asm("fma.rn.f32x2 %0, %1, %2, %0;" : "+l"(acc0[2*p])   : "l"(w20), "l"(a0));
                asm("fma.rn.f32x2 %0, %1, %2, %0;" : "+l"(acc0[2*p+1]) : "l"(w20), "l"(a1));
                asm("fma.rn.f32x2 %0, %1, %2, %0;" : "+l"(acc1[2*p])   : "l"(w21), "l"(a0));
                asm("fma.rn.f32x2 %0, %1, %2, %0;" : "+l"(acc1[2*p+1]) : "l"(w21), "l"(a1));
            }
        }
        __syncwarp();   // all lanes done with buf before it is refilled
    }
    #undef PREFETCH

    // ---------------- cross-warp tree reduction (3 rounds) -------------------
    #define WRITE_P(BUFI)                                                        \
        do {                                                                     \
            unsigned long long* d0 = &sm.red[BUFI][l][0];                        \
            unsigned long long* d1 = &sm.red[BUFI][32 + l][0];                   \
            _Pragma("unroll")                                                    \
            for (int p = 0; p < 16; ++p) { d0[p] = acc0[p]; d1[p] = acc1[p]; }   \
            ((float*)&d0[16])[0] = denom0;                                       \
            ((float*)&d1[16])[0] = denom1;                                       \
        } while (0)
    #define ADD_P(BUFI)                                                         \
        do {                                                                    \
            const unsigned long long* s0 = &sm.red[BUFI][l][0];                 \
            const unsigned long long* s1 = &sm.red[BUFI][32 + l][0];            \
            _Pragma("unroll")                                                   \
            for (int p = 0; p < 16; ++p) {                                      \
                asm("add.rn.f32x2 %0, %0, %1;" : "+l"(acc0[p]) : "l"(s0[p]));   \
                asm("add.rn.f32x2 %0, %0, %1;" : "+l"(acc1[p]) : "l"(s1[p]));   \
            }                                                                   \
            denom0 += ((const float*)&s0[16])[0];                               \
            denom1 += ((const float*)&s1[16])[0];                               \
        } while (0)

    __syncthreads();
    if (w & 1) WRITE_P(w >> 1);
    __syncthreads();
    if (!(w & 1)) ADD_P(w >> 1);
    __syncthreads();
    if (w == 2) WRITE_P(0);
    if (w == 6) WRITE_P(1);
    __syncthreads();
    if (w == 0) ADD_P(0);
    if (w == 4) ADD_P(1);
    __syncthreads();
    if (w == 4) WRITE_P(0);
    __syncthreads();

    if (w == 0) {
        ADD_P(0);
        const float inv0 = 1.0f / denom0;
        const float inv1 = 1.0f / denom1;
        float* dst0 = out + ((size_t)b * NN + i0 + l)      * DOUT + hh * HD;
        float* dst1 = out + ((size_t)b * NN + i0 + 32 + l) * DOUT + hh * HD;
        #pragma unroll
        for (int p = 0; p < 8; ++p) {
            float x0, y0, x1, y1;
            asm("mov.b64 {%0, %1}, %2;" : "=f"(x0), "=f"(y0) : "l"(acc0[2*p]));
            asm("mov.b64 {%0, %1}, %2;" : "=f"(x1), "=f"(y1) : "l"(acc0[2*p+1]));
            *(float4*)(dst0 + p * 4) = make_float4(x0*inv0, y0*inv0, x1*inv0, y1*inv0);
            asm("mov.b64 {%0, %1}, %2;" : "=f"(x0), "=f"(y0) : "l"(acc1[2*p]));
            asm("mov.b64 {%0, %1}, %2;" : "=f"(x1), "=f"(y1) : "l"(acc1[2*p+1]));
            *(float4*)(dst1 + p * 4) = make_float4(x0*inv1, y0*inv1, x1*inv1, y1*inv1);
        }
    }
    #undef WRITE_P
    #undef ADD_P
}

// ---------------- launch ------------------------------------------------------
extern "C" void kernel_launch(void* const* d_in, const int* in_sizes, int n_in,
                              void* d_out, int out_size) {
    const float* x   = (const float*)d_in[0];   // (B,N,DIN) f32
    const int*   adj = (const int*)  d_in[1];   // (N,N) i32
    const float* W   = (const float*)d_in[2];   // (H*HD, DIN) f32
    const float* a   = (const float*)d_in[3];   // (H, 2*HD, 1) f32
    float* out = (float*)d_out;                 // (B,N,H*HD) f32

    gemm_h_kernel<<<(BB * NN) / 32, 128>>>(x, W, a);
    adjt_kernel<<<dim3(NN / 32, NN / 32), dim3(32, 32)>>>(adj);
    gat_main_kernel<<<dim3(NN / 64, HH, BB), 256>>>(out);
}

// round 17
// speedup vs baseline: 1.7228x; 1.6504x over previous
#include <cuda_runtime.h>
#include <cstdint>

#define BB   4
#define NN   2048
#define DIN  128
#define DOUT 128      // H*HD
#define HH   4
#define HD   32
#define NWRD 64       // adj words per row
#define NCH  32       // 2048/64 j-chunks
#define LOG2E 1.4426950408889634f

// ---------------- scratch ------------------------------------------------------
__device__ float    g_h  [BB*NN*DOUT];  // 4 MB, tf32-rounded h = x @ W^T
__device__ float    g_ei2[HH*BB*NN];    // head-major, pre-scaled by log2e
__device__ float    g_ej2[HH*BB*NN];
__device__ unsigned g_adjP[NN*NWRD];    // bit k of word [i][jw] = adj[i][jw*32+k]

#define CP_ASYNC16(s, g) asm volatile("cp.async.ca.shared.global [%0], [%1], 16;" :: "r"(s), "l"(g))
#define CP_ASYNC8(s, g)  asm volatile("cp.async.ca.shared.global [%0], [%1], 8;"  :: "r"(s), "l"(g))

// ---------------- kernel 1: h = x @ W^T + fused ei/ej --------------------------
__global__ void __launch_bounds__(128) gemm_h_kernel(const float* __restrict__ x,
                                                     const float* __restrict__ W,
                                                     const float* __restrict__ a) {
    __shared__ __align__(16) float x_s[32][36];
    __shared__ __align__(16) float w_s[32][132];

    const int tid = threadIdx.x;
    const int cg  = tid & 31;
    const int rg  = tid >> 5;
    const int row0 = blockIdx.x * 32;

    float acc[8][4];
    #pragma unroll
    for (int r = 0; r < 8; ++r)
        #pragma unroll
        for (int c = 0; c < 4; ++c) acc[r][c] = 0.f;

    for (int k0 = 0; k0 < DIN; k0 += 32) {
        #pragma unroll
        for (int it = 0; it < 2; ++it) {
            int f = tid + it * 128;
            int r = f >> 3, q = f & 7;
            float4 v = *(const float4*)(x + (size_t)(row0 + r) * DIN + k0 + q * 4);
            *(float4*)&x_s[r][q * 4] = v;
        }
        {
            const float* wp = W + (size_t)tid * DIN + k0;
            #pragma unroll
            for (int kk = 0; kk < 32; kk += 4) {
                float4 v = *(const float4*)(wp + kk);
                w_s[kk + 0][tid] = v.x;
                w_s[kk + 1][tid] = v.y;
                w_s[kk + 2][tid] = v.z;
                w_s[kk + 3][tid] = v.w;
            }
        }
        __syncthreads();
        #pragma unroll
        for (int k = 0; k < 32; ++k) {
            float4 wv = *(const float4*)&w_s[k][cg * 4];
            #pragma unroll
            for (int r = 0; r < 8; ++r) {
                float xv = x_s[rg * 8 + r][k];
                acc[r][0] += xv * wv.x;
                acc[r][1] += xv * wv.y;
                acc[r][2] += xv * wv.z;
                acc[r][3] += xv * wv.w;
            }
        }
        __syncthreads();
    }

    // store h, pre-rounded to tf32 (consumed only as MMA B operand)
    #pragma unroll
    for (int r = 0; r < 8; ++r) {
        uint4 u;
        asm("cvt.rna.tf32.f32 %0, %1;" : "=r"(u.x) : "f"(acc[r][0]));
        asm("cvt.rna.tf32.f32 %0, %1;" : "=r"(u.y) : "f"(acc[r][1]));
        asm("cvt.rna.tf32.f32 %0, %1;" : "=r"(u.z) : "f"(acc[r][2]));
        asm("cvt.rna.tf32.f32 %0, %1;" : "=r"(u.w) : "f"(acc[r][3]));
        *(uint4*)(g_h + (size_t)(row0 + rg * 8 + r) * DOUT + cg * 4) = u;
    }

    // fused ei/ej from full-precision acc
    const int head = cg >> 3;
    const int c0   = (cg & 7) * 4;
    float a1v[4], a2v[4];
    #pragma unroll
    for (int k = 0; k < 4; ++k) {
        a1v[k] = a[head * 2 * HD + c0 + k];
        a2v[k] = a[head * 2 * HD + HD + c0 + k];
    }
    #pragma unroll
    for (int r = 0; r < 8; ++r) {
        float p1 = acc[r][0] * a1v[0] + acc[r][1] * a1v[1]
                 + acc[r][2] * a1v[2] + acc[r][3] * a1v[3];
        float p2 = acc[r][0] * a2v[0] + acc[r][1] * a2v[1]
                 + acc[r][2] * a2v[2] + acc[r][3] * a2v[3];
        p1 += __shfl_down_sync(0xffffffffu, p1, 4, 8);
        p1 += __shfl_down_sync(0xffffffffu, p1, 2, 8);
        p1 += __shfl_down_sync(0xffffffffu, p1, 1, 8);
        p2 += __shfl_down_sync(0xffffffffu, p2, 4, 8);
        p2 += __shfl_down_sync(0xffffffffu, p2, 2, 8);
        p2 += __shfl_down_sync(0xffffffffu, p2, 1, 8);
        if ((cg & 7) == 0) {
            int bn = row0 + rg * 8 + r;
            int b  = bn >> 11, n = bn & 2047;
            g_ei2[(head * BB + b) * NN + n] = p1 * LOG2E;
            g_ej2[(head * BB + b) * NN + n] = p2 * LOG2E;
        }
    }
}

// ---------------- kernel 2: pack adj into bitmask (row-major) ------------------
__global__ void adjp_kernel(const int* __restrict__ adj) {
    const int tx = threadIdx.x, ty = threadIdx.y;
    const int j0 = blockIdx.x * 32;
    const int i  = blockIdx.y * 32 + ty;
    int val = adj[(size_t)i * NN + j0 + tx];
    unsigned m = __ballot_sync(0xffffffffu, val != 0);
    if (tx == 0) g_adjP[(size_t)i * NWRD + (j0 >> 5)] = m;
}

// ---------------- kernel 3: GAT via mma.sync tf32 (m16n8k8) --------------------
// CTA = (b, h, 128 i-rows), 128 thr = 4 warps; warp = 32 rows = 2 m-tiles.
// Per 64-j chunk: stage h(tf32)/ej/adj via cp.async (double buffer); per k8-step
// build A fragments (masked exp weights) in regs, B fragments via LDS, 8 HMMA.
__global__ void __launch_bounds__(128) gat_mma_kernel(float* __restrict__ out) {
    __shared__ __align__(16) float    hs  [2][64][40];  // pitch 40: B-frag LDS conflict-free
    __shared__ __align__(16) float    ejs [2][64];
    __shared__ __align__(16) unsigned adjc[2][128][2];

    const int b  = blockIdx.z;
    const int hh = blockIdx.y;
    const int i0 = blockIdx.x * 128;
    const int t  = threadIdx.x;
    const int w  = t >> 5;
    const int l  = t & 31;
    const int klo = l & 3;        // k within quad
    const int r   = l >> 2;       // row group 0..7
    const int row0 = w * 32;      // warp's first row

    // ei for this lane's 4 rows (r, r+8, r+16, r+24 within warp)
    float ei[4];
    #pragma unroll
    for (int t4 = 0; t4 < 4; ++t4)
        ei[t4] = g_ei2[(size_t)(hh * BB + b) * NN + i0 + row0 + r + 8 * t4];

    float d[2][4][4];
    #pragma unroll
    for (int mt = 0; mt < 2; ++mt)
        #pragma unroll
        for (int nt = 0; nt < 4; ++nt)
            #pragma unroll
            for (int q = 0; q < 4; ++q) d[mt][nt][q] = 0.f;
    float den[4] = {0.f, 0.f, 0.f, 0.f};

    const float* hsrc = g_h + (size_t)b * NN * DOUT + hh * HD;
    const float* ejsrc = g_ej2 + (size_t)(hh * BB + b) * NN;

    #define PREF(BUF, C)                                                          \
        do {                                                                      \
            const int j0c = (C) * 64;                                             \
            _Pragma("unroll")                                                     \
            for (int it = 0; it < 4; ++it) {                                      \
                int idx = t + it * 128;                                           \
                int jj = idx >> 3, q = idx & 7;                                   \
                unsigned sp = (unsigned)__cvta_generic_to_shared(                 \
                    &hs[BUF][jj][q * 4]);                                         \
                CP_ASYNC16(sp, hsrc + (size_t)(j0c + jj) * DOUT + q * 4);         \
            }                                                                     \
            if (t < 16) {                                                         \
                unsigned sp = (unsigned)__cvta_generic_to_shared(                 \
                    &ejs[BUF][t * 4]);                                            \
                CP_ASYNC16(sp, ejsrc + j0c + t * 4);                              \
            }                                                                     \
            {                                                                     \
                unsigned sp = (unsigned)__cvta_generic_to_shared(                 \
                    &adjc[BUF][t][0]);                                            \
                CP_ASYNC8(sp, g_adjP + (size_t)(i0 + t) * NWRD + (C) * 2);        \
            }                                                                     \
            asm volatile("cp.async.commit_group;");                               \
        } while (0)

    PREF(0, 0);

    for (int c = 0; c < NCH; ++c) {
        const int buf = c & 1;
        if (c + 1 < NCH) {
            PREF(buf ^ 1, c + 1);
            asm volatile("cp.async.wait_group 1;" ::: "memory");
        } else {
            asm volatile("cp.async.wait_group 0;" ::: "memory");
        }
        __syncthreads();

        // adjacency words for this lane's 4 rows (2 words = 64 j)
        unsigned aw[4][2];
        #pragma unroll
        for (int t4 = 0; t4 < 4; ++t4) {
            uint2 v = *(const uint2*)&adjc[buf][row0 + r + 8 * t4][0];
            aw[t4][0] = v.x;
            aw[t4][1] = v.y;
        }

        #pragma unroll
        for (int kk = 0; kk < 8; ++kk) {
            float ej0 = ejs[buf][kk * 8 + klo];
            float ej1 = ejs[buf][kk * 8 + klo + 4];

            // A fragments: masked exp weights, tf32 bit patterns
            unsigned va[4][2];
            #pragma unroll
            for (int t4 = 0; t4 < 4; ++t4) {
                unsigned sh = aw[t4][kk >> 2] >> (((kk & 3) * 8) + klo);
                float t0 = ei[t4] + ej0;
                float t1 = ei[t4] + ej1;
                float lk0 = fmaxf(t0, 0.2f * t0);
                float lk1 = fmaxf(t1, 0.2f * t1);
                float e0, e1;
                asm("ex2.approx.f32 %0, %1;" : "=f"(e0) : "f"(lk0));
                asm("ex2.approx.f32 %0, %1;" : "=f"(e1) : "f"(lk1));
                unsigned u0, u1;
                asm("cvt.rna.tf32.f32 %0, %1;" : "=r"(u0) : "f"(e0));
                asm("cvt.rna.tf32.f32 %0, %1;" : "=r"(u1) : "f"(e1));
                va[t4][0] = (sh & 1u)        ? u0 : 0u;
                va[t4][1] = ((sh >> 4) & 1u) ? u1 : 0u;
                den[t4] += __uint_as_float(va[t4][0]) + __uint_as_float(va[t4][1]);
            }

            // B fragments: h already tf32; conflict-free LDS (bank = 8*klo + r)
            unsigned bf[4][2];
            #pragma unroll
            for (int nt = 0; nt < 4; ++nt) {
                bf[nt][0] = __float_as_uint(hs[buf][kk * 8 + klo][nt * 8 + r]);
                bf[nt][1] = __float_as_uint(hs[buf][kk * 8 + klo + 4][nt * 8 + r]);
            }

            #pragma unroll
            for (int mt = 0; mt < 2; ++mt)
                #pragma unroll
                for (int nt = 0; nt < 4; ++nt)
                    asm volatile(
                        "mma.sync.aligned.m16n8k8.row.col.f32.tf32.tf32.f32 "
                        "{%0,%1,%2,%3}, {%4,%5,%6,%7}, {%8,%9}, {%0,%1,%2,%3};"
                        : "+f"(d[mt][nt][0]), "+f"(d[mt][nt][1]),
                          "+f"(d[mt][nt][2]), "+f"(d[mt][nt][3])
                        : "r"(va[2 * mt][0]), "r"(va[2 * mt + 1][0]),
                          "r"(va[2 * mt][1]), "r"(va[2 * mt + 1][1]),
                          "r"(bf[nt][0]), "r"(bf[nt][1]));
        }
        __syncthreads();   // all warps done with buf before it is refilled
    }
    #undef PREF

    // reduce denominators across the 4 lanes of each quad (all lanes get result)
    #pragma unroll
    for (int t4 = 0; t4 < 4; ++t4) {
        den[t4] += __shfl_xor_sync(0xffffffffu, den[t4], 1);
        den[t4] += __shfl_xor_sync(0xffffffffu, den[t4], 2);
    }
    float inv[4];
    #pragma unroll
    for (int t4 = 0; t4 < 4; ++t4) inv[t4] = 1.0f / den[t4];

    // store: D[mt] rows = row0 + mt*16 + {r, r+8}; cols = nt*8 + klo*2 + {0,1}
    #pragma unroll
    for (int mt = 0; mt < 2; ++mt) {
        const int gi0 = i0 + row0 + mt * 16 + r;
        float* dst0 = out + ((size_t)b * NN + gi0)     * DOUT + hh * HD;
        float* dst1 = out + ((size_t)b * NN + gi0 + 8) * DOUT + hh * HD;
        const float v0 = inv[2 * mt], v1 = inv[2 * mt + 1];
        #pragma unroll
        for (int nt = 0; nt < 4; ++nt) {
            const int col = nt * 8 + klo * 2;
            float2 p0 = make_float2(d[mt][nt][0] * v0, d[mt][nt][1] * v0);
            float2 p1 = make_float2(d[mt][nt][2] * v1, d[mt][nt][3] * v1);
            *(float2*)(dst0 + col) = p0;
            *(float2*)(dst1 + col) = p1;
        }
    }
}

// ---------------- launch --------------------------------------------------------
extern "C" void kernel_launch(void* const* d_in, const int* in_sizes, int n_in,
                              void* d_out, int out_size) {
    const float* x   = (const float*)d_in[0];   // (B,N,DIN) f32
    const int*   adj = (const int*)  d_in[1];   // (N,N) i32
    const float* W   = (const float*)d_in[2];   // (H*HD, DIN) f32
    const float* a   = (const float*)d_in[3];   // (H, 2*HD, 1) f32
    float* out = (float*)d_out;                 // (B,N,H*HD) f32

    gemm_h_kernel<<<(BB * NN) / 32, 128>>>(x, W, a);
    adjp_kernel<<<dim3(NN / 32, NN / 32), dim3(32, 32)>>>(adj);
    gat_mma_kernel<<<dim3(NN / 128, HH, BB), 128>>>(out);
}